// round 7
// baseline (speedup 1.0000x reference)
#include <cuda_runtime.h>

#define T_LEN 2048
#define HID   15
#define EDIM  300
#define G4    60            // 4*HID gates
#define TPAD  (T_LEN + 8)   // pad so prefetch never needs a branch

// Precomputed input-projection gates, padded: [2][TPAD][G4]
__device__ float g_pre[2 * TPAD * G4];
// Final hidden states of the two sequences
__device__ float g_hfin[2][16];

// ---------------------------------------------------------------------------
// Kernel 1: pre[s][t][j] = b_ih[j] + b_hh[j] + emb[tok]·W_ih[j]
// ---------------------------------------------------------------------------
__global__ void precompute_kernel(const int* __restrict__ s1,
                                  const int* __restrict__ s2,
                                  const float* __restrict__ emb,
                                  const float* __restrict__ W_ih,
                                  const float* __restrict__ b_ih,
                                  const float* __restrict__ b_hh) {
    __shared__ float4 semb[EDIM / 4];

    const int bid = blockIdx.x;
    const int s   = bid >> 11;
    const int t   = bid & (T_LEN - 1);
    const int tok = (s == 0) ? s1[t] : s2[t];

    const float4* erow = reinterpret_cast<const float4*>(emb + (long long)tok * EDIM);
    for (int i = threadIdx.x; i < EDIM / 4; i += blockDim.x)
        semb[i] = erow[i];
    __syncthreads();

    const int j = threadIdx.x;
    if (j < G4) {
        const float4* wrow = reinterpret_cast<const float4*>(W_ih + j * EDIM);
        float a0 = 0.f, a1 = 0.f, a2 = 0.f, a3 = 0.f;
        #pragma unroll 5
        for (int e = 0; e < EDIM / 4; e++) {
            float4 wv = wrow[e];
            float4 xv = semb[e];
            a0 = fmaf(wv.x, xv.x, a0);
            a1 = fmaf(wv.y, xv.y, a1);
            a2 = fmaf(wv.z, xv.z, a2);
            a3 = fmaf(wv.w, xv.w, a3);
        }
        g_pre[(s * TPAD + t) * G4 + j] = b_ih[j] + b_hh[j] + ((a0 + a1) + (a2 + a3));
    }
}

// Hardware tanh (single MUFU.TANH, lat ~16)
__device__ __forceinline__ float tanhfast(float x) {
    float y; asm("tanh.approx.f32 %0, %1;" : "=f"(y) : "f"(x)); return y;
}

// ---------------------------------------------------------------------------
// Kernel 2: ONE LSTM recurrence per block (grid=2, 1 warp each -> different
// SMs, no shuffle/MUFU contention between the two sequences).
// Lane k<15:  gates i_k (row k),    g_k (row 30+k); holds state h_k, c_k.
// Lane 16+k:  gates f_k (row 15+k), o_k (row 45+k).
// h broadcast via 15 pipelined SHFL.IDX (no smem, no barriers in loop).
// ---------------------------------------------------------------------------
__global__ __launch_bounds__(32, 1)
void recurrence_kernel(const float* __restrict__ W_hh,
                       const float* __restrict__ h1_0,
                       const float* __restrict__ c1_0,
                       const float* __restrict__ h2_0,
                       const float* __restrict__ c2_0) {
    const int w    = blockIdx.x;     // sequence index
    const int lane = threadIdx.x;

    const bool lowhalf = (lane < 16);
    const int  sub     = lowhalf ? lane : lane - 16;
    const bool valid   = (sub < HID);

    const int ia = valid ? (lowhalf ? sub      : 15 + sub) : 0;  // i / f
    const int ib = valid ? (lowhalf ? 30 + sub : 45 + sub) : 0;  // g / o

    float Wa[HID], Wb[HID];
    #pragma unroll
    for (int m = 0; m < HID; m++) {
        Wa[m] = valid ? W_hh[ia * HID + m] : 0.0f;
        Wb[m] = valid ? W_hh[ib * HID + m] : 0.0f;
    }

    // act_b:  low (g): tanh(ab) -> sc=1,  mb=1,   cb=0
    //         high(o): sigm(ab) -> sc=.5, mb=.5,  cb=.5
    const float sc = lowhalf ? 1.0f : 0.5f;
    const float mb = lowhalf ? 1.0f : 0.5f;
    const float cb = lowhalf ? 0.0f : 0.5f;

    const float* baseA = g_pre + w * (TPAD * G4) + ia;
    const float* baseB = g_pre + w * (TPAD * G4) + ib;

    const float* h0 = (w == 0) ? h1_0 : h2_0;
    const float* c0 = (w == 0) ? c1_0 : c2_0;
    float cval = (lowhalf && valid) ? c0[sub] : 0.0f;
    float hval = (lowhalf && valid) ? h0[sub] : 0.0f;  // lane k holds h_k

    // three-deep register prefetch of pre (pad absorbs overrun)
    float paC = baseA[0],      pbC = baseB[0];
    float paN = baseA[G4],     pbN = baseB[G4];
    float paM = baseA[2 * G4], pbM = baseB[2 * G4];
    int   off = 3 * G4;

    #pragma unroll 2
    for (int t = 0; t < T_LEN; t++) {
        const float pa = paC, pb = pbC;
        paC = paN; pbC = pbN;
        paN = paM; pbN = pbM;
        paM = __ldg(baseA + off);
        pbM = __ldg(baseB + off);
        off += G4;

        // broadcast h_0..h_14 (15 independent SHFL.IDX, pipelined)
        float h0v  = __shfl_sync(0xffffffffu, hval, 0);
        float h1v  = __shfl_sync(0xffffffffu, hval, 1);
        float h2v  = __shfl_sync(0xffffffffu, hval, 2);
        float h3v  = __shfl_sync(0xffffffffu, hval, 3);
        float h4v  = __shfl_sync(0xffffffffu, hval, 4);
        float h5v  = __shfl_sync(0xffffffffu, hval, 5);
        float h6v  = __shfl_sync(0xffffffffu, hval, 6);
        float h7v  = __shfl_sync(0xffffffffu, hval, 7);
        float h8v  = __shfl_sync(0xffffffffu, hval, 8);
        float h9v  = __shfl_sync(0xffffffffu, hval, 9);
        float h10v = __shfl_sync(0xffffffffu, hval, 10);
        float h11v = __shfl_sync(0xffffffffu, hval, 11);
        float h12v = __shfl_sync(0xffffffffu, hval, 12);
        float h13v = __shfl_sync(0xffffffffu, hval, 13);
        float h14v = __shfl_sync(0xffffffffu, hval, 14);

        // 4-way split dot products, consume shfl results in arrival order
        float a0 = fmaf(Wa[0], h0v, pa);
        float e0 = fmaf(Wb[0], h0v, pb);
        a0 = fmaf(Wa[1], h1v, a0);  e0 = fmaf(Wb[1], h1v, e0);
        float a1 = Wa[2] * h2v;     float e1 = Wb[2] * h2v;
        a1 = fmaf(Wa[3], h3v, a1);  e1 = fmaf(Wb[3], h3v, e1);
        float a2 = Wa[4] * h4v;     float e2 = Wb[4] * h4v;
        a2 = fmaf(Wa[5], h5v, a2);  e2 = fmaf(Wb[5], h5v, e2);
        float a3 = Wa[6] * h6v;     float e3 = Wb[6] * h6v;
        a3 = fmaf(Wa[7], h7v, a3);  e3 = fmaf(Wb[7], h7v, e3);
        a0 = fmaf(Wa[8], h8v, a0);  e0 = fmaf(Wb[8], h8v, e0);
        a1 = fmaf(Wa[9], h9v, a1);  e1 = fmaf(Wb[9], h9v, e1);
        a2 = fmaf(Wa[10], h10v, a2); e2 = fmaf(Wb[10], h10v, e2);
        a3 = fmaf(Wa[11], h11v, a3); e3 = fmaf(Wb[11], h11v, e3);
        a0 = fmaf(Wa[12], h12v, a0); e0 = fmaf(Wb[12], h12v, e0);
        a1 = fmaf(Wa[13], h13v, a1); e1 = fmaf(Wb[13], h13v, e1);
        a2 = fmaf(Wa[14], h14v, a2); e2 = fmaf(Wb[14], h14v, e2);
        float aa = (a0 + a1) + (a2 + a3);
        float ab = (e0 + e1) + (e2 + e3);

        // activations: act_a = sigmoid (i low / f high);
        //              act_b = tanh (g low) / sigmoid (o high), branchless
        float ta = tanhfast(0.5f * aa);
        float act_b = fmaf(mb, tanhfast(sc * ab), cb);
        float act_a = fmaf(0.5f, ta, 0.5f);

        // bring f,o to the state lanes
        float fv = __shfl_down_sync(0xffffffffu, act_a, 16);
        float ov = __shfl_down_sync(0xffffffffu, act_b, 16);

        float ig = act_a * act_b;              // i*g (valid on low lanes)
        cval = fmaf(fv, cval, ig);             // c' = f*c + i*g
        hval = ov * tanhfast(cval);            // h' = o * tanh(c')
    }

    if (lowhalf && valid) g_hfin[w][sub] = hval;
}

// ---------------------------------------------------------------------------
// Kernel 3: tiny final MLP (1 warp).
// ---------------------------------------------------------------------------
__global__ __launch_bounds__(32, 1)
void mlp_kernel(const float* __restrict__ W1,
                const float* __restrict__ b1,
                const float* __restrict__ W2,
                const float* __restrict__ b2,
                float* __restrict__ out) {
    const int tid = threadIdx.x;
    __shared__ float sh_hidden[32];

    if (tid < 25) {
        const float* w1r = W1 + tid * (5 * HID);
        float acc = b1[tid];
        #pragma unroll
        for (int kk = 0; kk < HID; kk++) {
            float v1 = g_hfin[0][kk];
            float v2 = g_hfin[1][kk];
            acc = fmaf(w1r[kk],           v1,               acc);
            acc = fmaf(w1r[HID + kk],     fabsf(v1 - v2),   acc);
            acc = fmaf(w1r[2 * HID + kk], v2,               acc);
            acc = fmaf(w1r[3 * HID + kk], v1 * v2,          acc);
            acc = fmaf(w1r[4 * HID + kk], 0.5f * (v1 + v2), acc);
        }
        sh_hidden[tid] = acc;
    }
    __syncwarp();

    if (tid < 2) {
        float acc = b2[tid];
        #pragma unroll
        for (int j = 0; j < 25; j++)
            acc = fmaf(W2[tid * 25 + j], sh_hidden[j], acc);
        out[tid] = acc;
    }
}

extern "C" void kernel_launch(void* const* d_in, const int* in_sizes, int n_in,
                              void* d_out, int out_size) {
    const int*   s1   = (const int*)  d_in[0];
    const int*   s2   = (const int*)  d_in[1];
    const float* emb  = (const float*)d_in[2];
    const float* W_ih = (const float*)d_in[3];
    const float* W_hh = (const float*)d_in[4];
    const float* b_ih = (const float*)d_in[5];
    const float* b_hh = (const float*)d_in[6];
    const float* W1   = (const float*)d_in[7];
    const float* b1   = (const float*)d_in[8];
    const float* W2   = (const float*)d_in[9];
    const float* b2   = (const float*)d_in[10];
    const float* h1_0 = (const float*)d_in[11];
    const float* c1_0 = (const float*)d_in[12];
    const float* h2_0 = (const float*)d_in[13];
    const float* c2_0 = (const float*)d_in[14];
    float* out = (float*)d_out;

    precompute_kernel<<<2 * T_LEN, 64>>>(s1, s2, emb, W_ih, b_ih, b_hh);
    recurrence_kernel<<<2, 32>>>(W_hh, h1_0, c1_0, h2_0, c2_0);
    mlp_kernel<<<1, 32>>>(W1, b1, W2, b2, out);
}

// round 9
// speedup vs baseline: 1.4478x; 1.4478x over previous
#include <cuda_runtime.h>

#define T_LEN 2048
#define HID   15
#define EDIM  300
#define G4    60            // 4*HID gates
#define TPAD  (T_LEN + 8)   // pad so prefetch never needs a branch

// Precomputed input-projection gates, padded: [2][TPAD][G4]
__device__ float g_pre[2 * TPAD * G4];

// ---------------------------------------------------------------------------
// Kernel 1: pre[s][t][j] = b_ih[j] + b_hh[j] + emb[tok]·W_ih[j]
// ---------------------------------------------------------------------------
__global__ void precompute_kernel(const int* __restrict__ s1,
                                  const int* __restrict__ s2,
                                  const float* __restrict__ emb,
                                  const float* __restrict__ W_ih,
                                  const float* __restrict__ b_ih,
                                  const float* __restrict__ b_hh) {
    __shared__ float4 semb[EDIM / 4];

    const int bid = blockIdx.x;
    const int s   = bid >> 11;
    const int t   = bid & (T_LEN - 1);
    const int tok = (s == 0) ? s1[t] : s2[t];

    const float4* erow = reinterpret_cast<const float4*>(emb + (long long)tok * EDIM);
    for (int i = threadIdx.x; i < EDIM / 4; i += blockDim.x)
        semb[i] = erow[i];
    __syncthreads();

    const int j = threadIdx.x;
    if (j < G4) {
        const float4* wrow = reinterpret_cast<const float4*>(W_ih + j * EDIM);
        float a0 = 0.f, a1 = 0.f, a2 = 0.f, a3 = 0.f;
        #pragma unroll 5
        for (int e = 0; e < EDIM / 4; e++) {
            float4 wv = wrow[e];
            float4 xv = semb[e];
            a0 = fmaf(wv.x, xv.x, a0);
            a1 = fmaf(wv.y, xv.y, a1);
            a2 = fmaf(wv.z, xv.z, a2);
            a3 = fmaf(wv.w, xv.w, a3);
        }
        g_pre[(s * TPAD + t) * G4 + j] = b_ih[j] + b_hh[j] + ((a0 + a1) + (a2 + a3));
    }
}

// Hardware tanh (single MUFU.TANH)
__device__ __forceinline__ float tanhfast(float x) {
    float y; asm("tanh.approx.f32 %0, %1;" : "=f"(y) : "f"(x)); return y;
}

// ---------------------------------------------------------------------------
// Kernel 2: both LSTM recurrences (1 warp each, same block) + fused MLP.
// Lane k<15:  gates i_k (row k),    g_k (row 30+k); holds state h_k, c_k.
// Lane 16+k:  gates f_k (row 15+k), o_k (row 45+k).
// h broadcast via smem: ALL 32 lanes STS (no divergence); lanes 16-31 and
// lane 15 write junk to slots the dot tree either ignores or multiplies by a
// zero weight.  4x LDS.128 broadcast reads. One __syncwarp per step.
// ---------------------------------------------------------------------------
__global__ __launch_bounds__(64, 1)
void recurrence_kernel(const float* __restrict__ W_hh,
                       const float* __restrict__ W1,
                       const float* __restrict__ b1,
                       const float* __restrict__ W2,
                       const float* __restrict__ b2,
                       const float* __restrict__ h1_0,
                       const float* __restrict__ c1_0,
                       const float* __restrict__ h2_0,
                       const float* __restrict__ c2_0,
                       float* __restrict__ out) {
    const int tid  = threadIdx.x;
    const int w    = tid >> 5;
    const int lane = tid & 31;

    __shared__ __align__(16) float shh[2][32];   // per-warp h slots
    __shared__ float sh_h[2][16];
    __shared__ float sh_hidden[25];

    const bool lowhalf = (lane < 16);
    const int  sub     = lowhalf ? lane : lane - 16;
    const bool valid   = (sub < HID);

    const int ia = valid ? (lowhalf ? sub      : 15 + sub) : 0;  // i / f
    const int ib = valid ? (lowhalf ? 30 + sub : 45 + sub) : 0;  // g / o

    // Recurrent weight rows (16-wide, slot 15 = 0 so junk h[15] contributes 0)
    float Wa[16], Wb[16];
    #pragma unroll
    for (int m = 0; m < HID; m++) {
        Wa[m] = valid ? W_hh[ia * HID + m] : 0.0f;
        Wb[m] = valid ? W_hh[ib * HID + m] : 0.0f;
    }
    Wa[15] = 0.0f; Wb[15] = 0.0f;

    // act_b:  low (g): tanh(ab) -> sc=1,  mb=1,   cb=0
    //         high(o): sigm(ab) -> sc=.5, mb=.5,  cb=.5
    const float sc = lowhalf ? 1.0f : 0.5f;
    const float mb = lowhalf ? 1.0f : 0.5f;
    const float cb = lowhalf ? 0.0f : 0.5f;

    const float* baseA = g_pre + w * (TPAD * G4) + ia;
    const float* baseB = g_pre + w * (TPAD * G4) + ib;

    const float* h0p = (w == 0) ? h1_0 : h2_0;
    const float* c0p = (w == 0) ? c1_0 : c2_0;
    float cval = (lowhalf && valid) ? c0p[sub] : 0.0f;
    float hval = (lowhalf && valid) ? h0p[sub] : 0.0f;

    // all lanes store (no divergence); only slots 0..14 are meaningful
    shh[w][lane] = hval;
    __syncthreads();

    // three-deep register prefetch of pre (pad absorbs overrun)
    float paC = baseA[0],      pbC = baseB[0];
    float paN = baseA[G4],     pbN = baseB[G4];
    float paM = baseA[2 * G4], pbM = baseB[2 * G4];
    int   off = 3 * G4;

    const float4* s4 = reinterpret_cast<const float4*>(shh[w]);

    #pragma unroll 2
    for (int t = 0; t < T_LEN; t++) {
        const float pa = paC, pb = pbC;
        paC = paN; pbC = pbN;
        paN = paM; pbN = pbM;
        paM = __ldg(baseA + off);
        pbM = __ldg(baseB + off);
        off += G4;

        __syncwarp();
        // 4x LDS.128, all lanes same address -> conflict-free broadcast
        float4 H0 = s4[0], H1 = s4[1], H2 = s4[2], H3 = s4[3];

        // 4-way split dot products over 16 terms (term 15 has zero weight)
        float a0 = fmaf(Wa[0],  H0.x, pa);  float e0 = fmaf(Wb[0],  H0.x, pb);
        float a1 = Wa[1] * H0.y;            float e1 = Wb[1] * H0.y;
        float a2 = Wa[2] * H0.z;            float e2 = Wb[2] * H0.z;
        float a3 = Wa[3] * H0.w;            float e3 = Wb[3] * H0.w;
        a0 = fmaf(Wa[4],  H1.x, a0);        e0 = fmaf(Wb[4],  H1.x, e0);
        a1 = fmaf(Wa[5],  H1.y, a1);        e1 = fmaf(Wb[5],  H1.y, e1);
        a2 = fmaf(Wa[6],  H1.z, a2);        e2 = fmaf(Wb[6],  H1.z, e2);
        a3 = fmaf(Wa[7],  H1.w, a3);        e3 = fmaf(Wb[7],  H1.w, e3);
        a0 = fmaf(Wa[8],  H2.x, a0);        e0 = fmaf(Wb[8],  H2.x, e0);
        a1 = fmaf(Wa[9],  H2.y, a1);        e1 = fmaf(Wb[9],  H2.y, e1);
        a2 = fmaf(Wa[10], H2.z, a2);        e2 = fmaf(Wb[10], H2.z, e2);
        a3 = fmaf(Wa[11], H2.w, a3);        e3 = fmaf(Wb[11], H2.w, e3);
        a0 = fmaf(Wa[12], H3.x, a0);        e0 = fmaf(Wb[12], H3.x, e0);
        a1 = fmaf(Wa[13], H3.y, a1);        e1 = fmaf(Wb[13], H3.y, e1);
        a2 = fmaf(Wa[14], H3.z, a2);        e2 = fmaf(Wb[14], H3.z, e2);
        float aa = (a0 + a1) + (a2 + a3);
        float ab = (e0 + e1) + (e2 + e3);

        // activations: act_a = sigmoid (i low / f high);
        //              act_b = tanh (g low) / sigmoid (o high), branchless
        float ta = tanhfast(0.5f * aa);
        float act_b = fmaf(mb, tanhfast(sc * ab), cb);
        float act_a = fmaf(0.5f, ta, 0.5f);

        // bring f,o to the state lanes (single shfl pair)
        float fv = __shfl_down_sync(0xffffffffu, act_a, 16);
        float ov = __shfl_down_sync(0xffffffffu, act_b, 16);

        float ig = act_a * act_b;              // i*g (valid on low lanes)
        cval = fmaf(fv, cval, ig);             // c' = f*c + i*g
        hval = ov * tanhfast(cval);            // h' = o * tanh(c')

        shh[w][lane] = hval;                   // unconditional STS
    }

    // ---- fused final MLP ----
    if (lowhalf && valid) sh_h[w][sub] = hval;
    __syncthreads();

    if (tid < 25) {
        const float* w1r = W1 + tid * (5 * HID);
        float acc = b1[tid];
        #pragma unroll
        for (int kk = 0; kk < HID; kk++) {
            float v1 = sh_h[0][kk];
            float v2 = sh_h[1][kk];
            acc = fmaf(w1r[kk],           v1,               acc);
            acc = fmaf(w1r[HID + kk],     fabsf(v1 - v2),   acc);
            acc = fmaf(w1r[2 * HID + kk], v2,               acc);
            acc = fmaf(w1r[3 * HID + kk], v1 * v2,          acc);
            acc = fmaf(w1r[4 * HID + kk], 0.5f * (v1 + v2), acc);
        }
        sh_hidden[tid] = acc;
    }
    __syncthreads();

    if (tid < 2) {
        float acc = b2[tid];
        #pragma unroll
        for (int j = 0; j < 25; j++)
            acc = fmaf(W2[tid * 25 + j], sh_hidden[j], acc);
        out[tid] = acc;
    }
}

extern "C" void kernel_launch(void* const* d_in, const int* in_sizes, int n_in,
                              void* d_out, int out_size) {
    const int*   s1   = (const int*)  d_in[0];
    const int*   s2   = (const int*)  d_in[1];
    const float* emb  = (const float*)d_in[2];
    const float* W_ih = (const float*)d_in[3];
    const float* W_hh = (const float*)d_in[4];
    const float* b_ih = (const float*)d_in[5];
    const float* b_hh = (const float*)d_in[6];
    const float* W1   = (const float*)d_in[7];
    const float* b1   = (const float*)d_in[8];
    const float* W2   = (const float*)d_in[9];
    const float* b2   = (const float*)d_in[10];
    const float* h1_0 = (const float*)d_in[11];
    const float* c1_0 = (const float*)d_in[12];
    const float* h2_0 = (const float*)d_in[13];
    const float* c2_0 = (const float*)d_in[14];
    float* out = (float*)d_out;

    precompute_kernel<<<2 * T_LEN, 64>>>(s1, s2, emb, W_ih, b_ih, b_hh);
    recurrence_kernel<<<1, 64>>>(W_hh, W1, b1, W2, b2,
                                 h1_0, c1_0, h2_0, c2_0, out);
}